// round 5
// baseline (speedup 1.0000x reference)
#include <cuda_runtime.h>
#include <cstdint>

// ---------------- configuration (fixed for this problem instance) ----------------
#define OUT_DIM   640           // rep_dim = out_dim for METADATA [64,64,32,32]
#define NG        (OUT_DIM/32)  // 20 output groups of 32
#define ROWS      16            // batch rows per main-kernel block
#define KCAP      20            // max terms per single output (measured ~16)
#define MAX_M     8192          // cap on number of sparse terms (actual ~4.7K)

// ---------------- device scratch (no runtime allocation allowed) ----------------
__device__ int      d_maxlen[NG];                 // padded segment length per group
__device__ unsigned d_ell_idx[NG * KCAP * 32];    // packed (r1 | r2<<16), [group][k][lane]
__device__ float    d_ell_cg [NG * KCAP * 32];    // cg coefficient (0 = padding)

// ---------------- single preprocessing kernel ----------------
// One block per output group. Stage ro in smem; 8 warps two-pass scan:
// pass1 counts matches per lane-output per warp-slice, smem exchange gives
// deterministic exclusive offsets (slot = rank of term in m-order), pass2
// scatters entries. Warp 0 pads lanes up to the group max and writes maxlen.
__global__ __launch_bounds__(256) void k_prep(const int* __restrict__ ro,
                                              const int* __restrict__ r1,
                                              const int* __restrict__ r2,
                                              const float* __restrict__ cg,
                                              int M) {
    __shared__ int s_ro[MAX_M];
    __shared__ int s_cnt[8][32];
    int og = blockIdx.x;

    for (int i = threadIdx.x; i < M; i += 256) s_ro[i] = ro[i];
    __syncthreads();

    int w = threadIdx.x >> 5, lane = threadIdx.x & 31;
    int o = og * 32 + lane;
    int chunk = (M + 7) >> 3;
    int mlo = w * chunk;
    int mhi = mlo + chunk; if (mhi > M) mhi = M;

    // pass 1: count
    int cnt = 0;
    for (int m = mlo; m < mhi; m++) cnt += (s_ro[m] == o);
    s_cnt[w][lane] = cnt;
    __syncthreads();

    // exclusive offset across warps (deterministic)
    int off = 0;
    #pragma unroll
    for (int ww = 0; ww < 8; ww++)
        if (ww < w) off += s_cnt[ww][lane];

    // pass 2: scatter
    int k = off;
    for (int m = mlo; m < mhi; m++) {
        if (s_ro[m] == o) {
            if (k < KCAP) {
                int pos = (og * KCAP + k) * 32 + lane;
                d_ell_idx[pos] = ((unsigned)r1[m] & 0xFFFFu) |
                                 (((unsigned)r2[m] & 0xFFFFu) << 16);
                d_ell_cg[pos] = cg[m];
            }
            k++;
        }
    }

    // warp 0: totals -> group len -> padding (disjoint slots, no sync needed)
    if (w == 0) {
        int tot = 0;
        #pragma unroll
        for (int ww = 0; ww < 8; ww++) tot += s_cnt[ww][lane];
        if (tot > KCAP) tot = KCAP;
        int len = tot;
        #pragma unroll
        for (int s = 16; s; s >>= 1)
            len = max(len, __shfl_xor_sync(0xFFFFFFFFu, len, s));
        if (lane == 0) d_maxlen[og] = len;
        for (int kk = tot; kk < len; kk++) {
            int pos = (og * KCAP + kk) * 32 + lane;
            d_ell_idx[pos] = 0u;
            d_ell_cg[pos] = 0.0f;
        }
    }
}

// ---------------- main kernel ----------------
// Block: 256 threads (8 warps), ROWS=16 batch rows staged in smem (80 KB).
// Each warp owns 2 rows; lanes = the 32 outputs of the current group.
// Gathers are conflict-free LDS (consecutive lanes -> consecutive addresses),
// ELL index loads are coalesced 128B L1-resident, stores coalesced, no atomics.
__global__ __launch_bounds__(256) void k_main(const float* __restrict__ x1,
                                              const float* __restrict__ x2,
                                              float* __restrict__ out, int N) {
    extern __shared__ float sm[];
    float* x1s = sm;                   // [ROWS][640]
    float* x2s = sm + ROWS * OUT_DIM;  // [ROWS][640]
    __shared__ int s_len[NG];

    int row0 = blockIdx.x * ROWS;
    int rows_here = N - row0;
    if (rows_here > ROWS) rows_here = ROWS;

    if (threadIdx.x < NG) s_len[threadIdx.x] = d_maxlen[threadIdx.x];

    {
        const float4* g1 = (const float4*)(x1 + (size_t)row0 * OUT_DIM);
        const float4* g2 = (const float4*)(x2 + (size_t)row0 * OUT_DIM);
        float4* s1 = (float4*)x1s;
        float4* s2 = (float4*)x2s;
        int n4 = rows_here * (OUT_DIM / 4);
        for (int i = threadIdx.x; i < n4; i += blockDim.x) {
            s1[i] = g1[i];
            s2[i] = g2[i];
        }
    }
    __syncthreads();

    int wid = threadIdx.x >> 5, lane = threadIdx.x & 31;
    int r_local = wid * 2;
    bool has0 = (row0 + r_local) < N;
    bool has1 = (row0 + r_local + 1) < N;

    const float* a0 = x1s + r_local * OUT_DIM;
    const float* a1 = a0 + OUT_DIM;
    const float* b0 = x2s + r_local * OUT_DIM;
    const float* b1 = b0 + OUT_DIM;
    float* o0 = out + (size_t)(row0 + r_local) * OUT_DIM;

    #pragma unroll 1
    for (int og = 0; og < NG; og++) {
        int len = s_len[og];
        const unsigned* ip = d_ell_idx + (size_t)og * KCAP * 32 + lane;
        const float*    cp = d_ell_cg  + (size_t)og * KCAP * 32 + lane;
        float acc0 = 0.0f, acc1 = 0.0f;
        #pragma unroll 2
        for (int k = 0; k < len; k++) {
            unsigned p = ip[k * 32];
            float    c = cp[k * 32];
            int i1 = (int)(p & 0xFFFFu);
            int i2 = (int)(p >> 16);
            acc0 = fmaf(c * a0[i1], b0[i2], acc0);
            acc1 = fmaf(c * a1[i1], b1[i2], acc1);
        }
        int ocol = og * 32 + lane;
        if (has0) o0[ocol] = acc0;
        if (has1) o0[OUT_DIM + ocol] = acc1;
    }
}

// ---------------- launch ----------------
extern "C" void kernel_launch(void* const* d_in, const int* in_sizes, int n_in,
                              void* d_out, int out_size) {
    const float* x1 = (const float*)d_in[0];
    const float* x2 = (const float*)d_in[1];
    const float* cg = (const float*)d_in[2];
    const int*   r1 = (const int*)d_in[3];
    const int*   r2 = (const int*)d_in[4];
    const int*   ro = (const int*)d_in[5];

    int M = in_sizes[2];
    if (M > MAX_M) M = MAX_M;   // safety (actual M ~ 4.7K)
    int N = out_size / OUT_DIM;

    k_prep<<<NG, 256>>>(ro, r1, r2, cg, M);

    size_t smem = (size_t)2 * ROWS * OUT_DIM * sizeof(float);  // 80 KB
    cudaFuncSetAttribute(k_main, cudaFuncAttributeMaxDynamicSharedMemorySize,
                         (int)smem);
    int nblocks = (N + ROWS - 1) / ROWS;
    k_main<<<nblocks, 256, smem>>>(x1, x2, (float*)d_out, N);
}

// round 8
// speedup vs baseline: 1.4241x; 1.4241x over previous
#include <cuda_runtime.h>
#include <cstdint>

// ---------------- configuration (fixed for this problem instance) ----------------
#define OUT_DIM   640           // rep_dim = out_dim for METADATA [64,64,32,32]
#define NG        (OUT_DIM/32)  // 20 output groups of 32
#define GSPLIT    (NG/2)        // groups per warp (2 warps share a row-pair)
#define ROWS      8             // batch rows per main-kernel block (4 pairs)
#define KCAP      20            // max terms per single output (measured ~16)
#define MAX_M     8192          // cap on number of sparse terms (actual ~4.7K)

// ---------------- device scratch (no runtime allocation allowed) ----------------
__device__ int                d_maxlen[NG];              // padded length per group
__device__ unsigned long long d_ell_meta[NG * KCAP * 32]; // (cg_bits<<32)|(r2<<16)|r1

// ---------------- single preprocessing kernel ----------------
// One block per output group. Stage ro in smem; 8 warps two-pass scan:
// pass1 counts matches per lane-output per warp-slice, smem exchange gives
// deterministic exclusive offsets (slot = rank of term in m-order), pass2
// scatters packed entries. Warp 0 pads lanes to the group max, writes maxlen.
__global__ __launch_bounds__(256) void k_prep(const int* __restrict__ ro,
                                              const int* __restrict__ r1,
                                              const int* __restrict__ r2,
                                              const float* __restrict__ cg,
                                              int M) {
    __shared__ int s_ro[MAX_M];
    __shared__ int s_cnt[8][32];
    int og = blockIdx.x;

    for (int i = threadIdx.x; i < M; i += 256) s_ro[i] = ro[i];
    __syncthreads();

    int w = threadIdx.x >> 5, lane = threadIdx.x & 31;
    int o = og * 32 + lane;
    int chunk = (M + 7) >> 3;
    int mlo = w * chunk;
    int mhi = mlo + chunk; if (mhi > M) mhi = M;

    int cnt = 0;
    for (int m = mlo; m < mhi; m++) cnt += (s_ro[m] == o);
    s_cnt[w][lane] = cnt;
    __syncthreads();

    int off = 0;
    #pragma unroll
    for (int ww = 0; ww < 8; ww++)
        if (ww < w) off += s_cnt[ww][lane];

    int k = off;
    for (int m = mlo; m < mhi; m++) {
        if (s_ro[m] == o) {
            if (k < KCAP) {
                unsigned pidx = ((unsigned)r1[m] & 0xFFFFu) |
                                (((unsigned)r2[m] & 0xFFFFu) << 16);
                unsigned cbits = __float_as_uint(cg[m]);
                d_ell_meta[(og * KCAP + k) * 32 + lane] =
                    ((unsigned long long)cbits << 32) | pidx;
            }
            k++;
        }
    }

    if (w == 0) {
        int tot = 0;
        #pragma unroll
        for (int ww = 0; ww < 8; ww++) tot += s_cnt[ww][lane];
        if (tot > KCAP) tot = KCAP;
        int len = tot;
        #pragma unroll
        for (int s = 16; s; s >>= 1)
            len = max(len, __shfl_xor_sync(0xFFFFFFFFu, len, s));
        if (lane == 0) d_maxlen[og] = len;
        for (int kk = tot; kk < len; kk++)
            d_ell_meta[(og * KCAP + kk) * 32 + lane] = 0ULL;  // cg=0 padding
    }
}

// ---------------- main kernel ----------------
// Block: 256 threads (8 warps), ROWS=8 rows (4 pairs) staged interleaved in
// 40KB smem -> 5 CTAs/SM (62.5% occupancy). Two warps share each row-pair,
// splitting the 20 output groups 10/10. Per term: 1 LDG.64 (packed meta,
// L1-resident), 2 LDS.64 (both rows at once, conflict-free), 4 FP ops.
// Coalesced stores, register accumulation, no atomics.
__global__ __launch_bounds__(256) void k_main(const float* __restrict__ x1,
                                              const float* __restrict__ x2,
                                              float* __restrict__ out, int N) {
    __shared__ float x1s[ROWS * OUT_DIM];   // [pair][col][r] interleaved
    __shared__ float x2s[ROWS * OUT_DIM];
    __shared__ int   s_len[NG];

    int row0 = blockIdx.x * ROWS;
    if (threadIdx.x < NG) s_len[threadIdx.x] = d_maxlen[threadIdx.x];

    // stage rows interleaved by pair: dst[pair*1280 + col*2 + (row&1)]
    {
        const float4* g1 = (const float4*)(x1 + (size_t)row0 * OUT_DIM);
        const float4* g2 = (const float4*)(x2 + (size_t)row0 * OUT_DIM);
        int rows_here = N - row0; if (rows_here > ROWS) rows_here = ROWS;
        int n4 = rows_here * (OUT_DIM / 4);
        for (int i = threadIdx.x; i < n4; i += 256) {
            int r  = i / (OUT_DIM / 4);
            int c4 = i - r * (OUT_DIM / 4);
            float4 v1 = g1[i];
            float4 v2 = g2[i];
            int base = (r >> 1) * (2 * OUT_DIM) + (c4 * 4) * 2 + (r & 1);
            x1s[base + 0] = v1.x; x1s[base + 2] = v1.y;
            x1s[base + 4] = v1.z; x1s[base + 6] = v1.w;
            x2s[base + 0] = v2.x; x2s[base + 2] = v2.y;
            x2s[base + 4] = v2.z; x2s[base + 6] = v2.w;
        }
    }
    __syncthreads();

    int w = threadIdx.x >> 5, lane = threadIdx.x & 31;
    int pair = w >> 1;
    int g0 = (w & 1) * GSPLIT;
    const float* a = x1s + pair * (2 * OUT_DIM);
    const float* b = x2s + pair * (2 * OUT_DIM);
    int row = row0 + pair * 2;
    bool has0 = row < N, has1 = (row + 1) < N;
    float* op = out + (size_t)row * OUT_DIM;

    #pragma unroll 1
    for (int og = g0; og < g0 + GSPLIT; og++) {
        int len = s_len[og];
        const unsigned long long* mp = d_ell_meta + (size_t)og * KCAP * 32 + lane;
        float acc0 = 0.0f, acc1 = 0.0f;
        #pragma unroll 4
        for (int k = 0; k < len; k++) {
            unsigned long long mv = mp[k * 32];
            unsigned pidx = (unsigned)mv;
            float c = __uint_as_float((unsigned)(mv >> 32));
            int i1 = (int)(pidx & 0xFFFFu);
            int i2 = (int)(pidx >> 16);
            float2 va = *(const float2*)(a + i1 * 2);
            float2 vb = *(const float2*)(b + i2 * 2);
            acc0 = fmaf(c * va.x, vb.x, acc0);
            acc1 = fmaf(c * va.y, vb.y, acc1);
        }
        int ocol = og * 32 + lane;
        if (has0) op[ocol] = acc0;
        if (has1) op[OUT_DIM + ocol] = acc1;
    }
}

// ---------------- launch ----------------
extern "C" void kernel_launch(void* const* d_in, const int* in_sizes, int n_in,
                              void* d_out, int out_size) {
    const float* x1 = (const float*)d_in[0];
    const float* x2 = (const float*)d_in[1];
    const float* cg = (const float*)d_in[2];
    const int*   r1 = (const int*)d_in[3];
    const int*   r2 = (const int*)d_in[4];
    const int*   ro = (const int*)d_in[5];

    int M = in_sizes[2];
    if (M > MAX_M) M = MAX_M;   // safety (actual M ~ 4.7K)
    int N = out_size / OUT_DIM;

    k_prep<<<NG, 256>>>(ro, r1, r2, cg, M);

    int nblocks = (N + ROWS - 1) / ROWS;
    k_main<<<nblocks, 256>>>(x1, x2, (float*)d_out, N);
}